// round 1
// baseline (speedup 1.0000x reference)
#include <cuda_runtime.h>

// splineGCN: 2-layer SplineConv (K=2, linear B-spline on 1-D pseudo coords)
// N=50000 nodes, E=1.6M edges, dims 32 -> 32 -> 10, log_softmax output.

#define NMAX 50000
#define EMAX 1600000

// ---- scratch (static device globals; no allocation allowed) ----
__device__ float g_h0  [NMAX * 32];  // x @ W1[0]
__device__ float g_hd  [NMAX * 32];  // x @ (W1[1]-W1[0])  (delta)
__device__ float g_r1  [NMAX * 32];  // x @ root1 + b1
__device__ float g_agg1[NMAX * 32];
__device__ float g_h   [NMAX * 32];  // relu output of layer 1
__device__ float g_g0  [NMAX * 16];  // h @ W2[0]   (stride 16, cols 10..15 zero)
__device__ float g_gd  [NMAX * 16];  // h @ (W2[1]-W2[0])
__device__ float g_r2  [NMAX * 16];  // h @ root2 + b2
__device__ float g_agg2[NMAX * 16];
__device__ float g_deg [NMAX];
__device__ int   g_is64;

// ---- dtype detection for edge_index (int64 vs canonicalized int32) ----
// Values are in [0, 50000) < 2^31. If stored as int64 (little-endian), every
// odd int32 word is 0. Probability that genuine int32 data has 32 consecutive
// odd-position zeros is ~(1/50000)^32 == never.
__global__ void k_detect(const void* __restrict__ ei) {
    const int* p = (const int*)ei;
    int ok64 = 1;
    #pragma unroll
    for (int i = 0; i < 32; ++i)
        if (p[2 * i + 1] != 0) ok64 = 0;
    g_is64 = ok64;
}

__global__ void k_zero(int n) {
    int idx = blockIdx.x * blockDim.x + threadIdx.x;
    if (idx < n * 32) g_agg1[idx] = 0.0f;
    if (idx < n * 16) g_agg2[idx] = 0.0f;
    if (idx < n)      g_deg[idx]  = 0.0f;
}

// ---- layer-1 node precompute: h0, h1-h0, x@root1+b1. One warp per node. ----
__global__ void k_prep1(const float* __restrict__ x,
                        const float* __restrict__ W1,     // (2,32,32)
                        const float* __restrict__ root1,  // (32,32)
                        const float* __restrict__ b1,     // (32)
                        int n) {
    __shared__ float sW0[1024], sW1[1024], sR[1024];
    for (int i = threadIdx.x; i < 1024; i += blockDim.x) {
        sW0[i] = W1[i];
        sW1[i] = W1[1024 + i];
        sR[i]  = root1[i];
    }
    __syncthreads();
    int lane = threadIdx.x & 31;
    int node = blockIdx.x * (blockDim.x >> 5) + (threadIdx.x >> 5);
    if (node >= n) return;
    float xv = x[node * 32 + lane];
    float a0 = 0.f, a1 = 0.f, ar = 0.f;
    #pragma unroll
    for (int k = 0; k < 32; ++k) {
        float xk = __shfl_sync(0xffffffffu, xv, k);
        a0 = fmaf(xk, sW0[k * 32 + lane], a0);
        a1 = fmaf(xk, sW1[k * 32 + lane], a1);
        ar = fmaf(xk, sR [k * 32 + lane], ar);
    }
    int o = node * 32 + lane;
    g_h0[o] = a0;
    g_hd[o] = a1 - a0;
    g_r1[o] = ar + b1[lane];
}

// ---- layer-1 edge scatter: one warp per edge, lane = feature ----
__global__ void k_edge1(const void* __restrict__ ei,
                        const float* __restrict__ ea, int E) {
    int w = (blockIdx.x * blockDim.x + threadIdx.x) >> 5;
    int lane = threadIdx.x & 31;
    if (w >= E) return;
    int src, dst;
    if (g_is64) {
        const long long* p = (const long long*)ei;
        src = (int)p[w]; dst = (int)p[E + w];
    } else {
        const int* p = (const int*)ei;
        src = p[w]; dst = p[E + w];
    }
    float u = ea[w];
    float a = g_h0[src * 32 + lane];
    float d = g_hd[src * 32 + lane];
    atomicAdd(&g_agg1[dst * 32 + lane], fmaf(u, d, a));
    if (lane == 0) atomicAdd(&g_deg[dst], 1.0f);
}

// ---- layer-1 combine: mean + root + bias, relu ----
__global__ void k_combine1(int n) {
    int idx = blockIdx.x * blockDim.x + threadIdx.x;
    if (idx >= n * 32) return;
    int i = idx >> 5;
    float inv = 1.0f / fmaxf(g_deg[i], 1.0f);
    float v = g_agg1[idx] * inv + g_r1[idx];
    g_h[idx] = fmaxf(v, 0.0f);
}

// ---- layer-2 node precompute: g0, g1-g0, h@root2+b2 (padded to 16 cols) ----
__global__ void k_prep2(const float* __restrict__ W2,     // (2,32,10)
                        const float* __restrict__ root2,  // (32,10)
                        const float* __restrict__ b2,     // (10)
                        int n) {
    __shared__ float sW0[512], sW1[512], sR[512];
    for (int i = threadIdx.x; i < 512; i += blockDim.x) {
        int k = i >> 4, j = i & 15;
        float w0 = 0.f, w1 = 0.f, r = 0.f;
        if (j < 10) {
            w0 = W2[k * 10 + j];
            w1 = W2[320 + k * 10 + j];
            r  = root2[k * 10 + j];
        }
        sW0[i] = w0; sW1[i] = w1; sR[i] = r;
    }
    __syncthreads();
    int lane = threadIdx.x & 31;
    int node = blockIdx.x * (blockDim.x >> 5) + (threadIdx.x >> 5);
    if (node >= n) return;
    float hv = g_h[node * 32 + lane];
    int j = lane & 15;
    float a0 = 0.f, a1 = 0.f, ar = 0.f;
    #pragma unroll
    for (int k = 0; k < 32; ++k) {
        float hk = __shfl_sync(0xffffffffu, hv, k);
        a0 = fmaf(hk, sW0[k * 16 + j], a0);
        a1 = fmaf(hk, sW1[k * 16 + j], a1);
        ar = fmaf(hk, sR [k * 16 + j], ar);
    }
    if (lane < 16) {
        int o = node * 16 + lane;
        g_g0[o] = a0;
        g_gd[o] = a1 - a0;
        g_r2[o] = ar + ((lane < 10) ? b2[lane] : 0.0f);
    }
}

// ---- layer-2 edge scatter: 16-lane sub-warp per edge (2 edges / warp) ----
__global__ void k_edge2(const void* __restrict__ ei,
                        const float* __restrict__ ea, int E) {
    int gw = (blockIdx.x * blockDim.x + threadIdx.x) >> 5;
    int lane = threadIdx.x & 31;
    int half = lane >> 4;
    int sl = lane & 15;
    int e = gw * 2 + half;
    if (e >= E) return;
    int src, dst;
    if (g_is64) {
        const long long* p = (const long long*)ei;
        src = (int)p[e]; dst = (int)p[E + e];
    } else {
        const int* p = (const int*)ei;
        src = p[e]; dst = p[E + e];
    }
    float u = ea[e];
    if (sl < 10) {
        float a = g_g0[src * 16 + sl];
        float d = g_gd[src * 16 + sl];
        atomicAdd(&g_agg2[dst * 16 + sl], fmaf(u, d, a));
    }
}

// ---- layer-2 combine + log_softmax. One thread per node. ----
__global__ void k_combine2(float* __restrict__ out, int n) {
    int i = blockIdx.x * blockDim.x + threadIdx.x;
    if (i >= n) return;
    float inv = 1.0f / fmaxf(g_deg[i], 1.0f);
    float z[10];
    float m = -1e30f;
    #pragma unroll
    for (int j = 0; j < 10; ++j) {
        z[j] = g_agg2[i * 16 + j] * inv + g_r2[i * 16 + j];
        m = fmaxf(m, z[j]);
    }
    float s = 0.f;
    #pragma unroll
    for (int j = 0; j < 10; ++j) s += __expf(z[j] - m);
    float l = m + logf(s);
    #pragma unroll
    for (int j = 0; j < 10; ++j) out[i * 10 + j] = z[j] - l;
}

extern "C" void kernel_launch(void* const* d_in, const int* in_sizes, int n_in,
                              void* d_out, int out_size) {
    const float* x     = (const float*)d_in[0];
    const void*  ei    = d_in[1];              // edge_index (2,E) int64 or int32
    const float* ea    = (const float*)d_in[2];
    const float* W1    = (const float*)d_in[3];
    const float* root1 = (const float*)d_in[4];
    const float* b1    = (const float*)d_in[5];
    const float* W2    = (const float*)d_in[6];
    const float* root2 = (const float*)d_in[7];
    const float* b2    = (const float*)d_in[8];
    float* out = (float*)d_out;

    int N = in_sizes[0] / 32;
    int E = in_sizes[2];        // edge_attr has E elements

    k_detect<<<1, 1>>>(ei);
    k_zero<<<(N * 32 + 255) / 256, 256>>>(N);
    k_prep1<<<(N + 7) / 8, 256>>>(x, W1, root1, b1, N);
    // warp per edge: E*32 threads
    {
        long long th = (long long)E * 32;
        int blocks = (int)((th + 255) / 256);
        k_edge1<<<blocks, 256>>>(ei, ea, E);
    }
    k_combine1<<<(N * 32 + 255) / 256, 256>>>(N);
    k_prep2<<<(N + 7) / 8, 256>>>(W2, root2, b2, N);
    // 2 edges per warp: E*16 threads
    {
        long long th = (long long)E * 16;
        int blocks = (int)((th + 255) / 256);
        k_edge2<<<blocks, 256>>>(ei, ea, E);
    }
    k_combine2<<<(N + 255) / 256, 256>>>(out, N);
}

// round 2
// speedup vs baseline: 1.6273x; 1.6273x over previous
#include <cuda_runtime.h>
#include <cuda_fp16.h>

// splineGCN: 2-layer SplineConv (K=2), N=50000, E=1.6M, 32 -> 32 -> 10, log_softmax.

#define NMAX 50000
#define EMAX 1600000

// ---- scratch ----
__device__ __half2 g_p1  [NMAX * 32];  // packed {h0, h1-h0} per (node, feat)
__device__ float   g_r1  [NMAX * 32];  // x @ root1 + b1
__device__ float   g_agg1[NMAX * 32];
__device__ float   g_h   [NMAX * 32];  // relu output of layer 1
__device__ __half2 g_p2  [NMAX * 16];  // packed {g0, g1-g0}, stride 16 (cols 10..15 zero)
__device__ float   g_r2  [NMAX * 16];
__device__ float   g_agg2[NMAX * 16];
__device__ float   g_deg [NMAX];
__device__ int2    g_eidx[EMAX];       // decoded (src, dst)
__device__ int     g_is64;

// ---- dtype detection: int64 edge_index has all odd 32-bit words zero ----
__global__ void k_detect(const void* __restrict__ ei) {
    const int* p = (const int*)ei;
    int ok64 = 1;
    #pragma unroll
    for (int i = 0; i < 32; ++i)
        if (p[2 * i + 1] != 0) ok64 = 0;
    g_is64 = ok64;
}

__global__ void k_zero(int n) {
    int idx = blockIdx.x * blockDim.x + threadIdx.x;
    if (idx < n * 32) g_agg1[idx] = 0.0f;
    if (idx < n * 16) g_agg2[idx] = 0.0f;
    if (idx < n)      g_deg[idx]  = 0.0f;
}

// ---- decode edge_index -> int2, accumulate degree (coalesced, thread/edge) ----
__global__ void k_decode(const void* __restrict__ ei, int E) {
    int e = blockIdx.x * blockDim.x + threadIdx.x;
    if (e >= E) return;
    int src, dst;
    if (g_is64) {
        const long long* p = (const long long*)ei;
        src = (int)p[e]; dst = (int)p[E + e];
    } else {
        const int* p = (const int*)ei;
        src = p[e]; dst = p[E + e];
    }
    g_eidx[e] = make_int2(src, dst);
    atomicAdd(&g_deg[dst], 1.0f);
}

// ---- layer-1 node precompute. One warp per node. ----
__global__ void k_prep1(const float* __restrict__ x,
                        const float* __restrict__ W1,     // (2,32,32)
                        const float* __restrict__ root1,  // (32,32)
                        const float* __restrict__ b1,
                        int n) {
    __shared__ float sW0[1024], sW1[1024], sR[1024];
    for (int i = threadIdx.x; i < 1024; i += blockDim.x) {
        sW0[i] = W1[i];
        sW1[i] = W1[1024 + i];
        sR[i]  = root1[i];
    }
    __syncthreads();
    int lane = threadIdx.x & 31;
    int node = blockIdx.x * (blockDim.x >> 5) + (threadIdx.x >> 5);
    if (node >= n) return;
    float xv = x[node * 32 + lane];
    float a0 = 0.f, a1 = 0.f, ar = 0.f;
    #pragma unroll
    for (int k = 0; k < 32; ++k) {
        float xk = __shfl_sync(0xffffffffu, xv, k);
        a0 = fmaf(xk, sW0[k * 32 + lane], a0);
        a1 = fmaf(xk, sW1[k * 32 + lane], a1);
        ar = fmaf(xk, sR [k * 32 + lane], ar);
    }
    int o = node * 32 + lane;
    g_p1[o] = __floats2half2_rn(a0, a1 - a0);
    g_r1[o] = ar + b1[lane];
}

// ---- layer-1 edge scatter: warp/4-edges, lane = feature, batched MLP ----
#define EPW1 4
__global__ void k_edge1(const float* __restrict__ ea, int E) {
    int w = (blockIdx.x * blockDim.x + threadIdx.x) >> 5;
    int lane = threadIdx.x & 31;
    int e0 = w * EPW1;
    if (e0 >= E) return;
    int2  idx[EPW1];
    float u  [EPW1];
    #pragma unroll
    for (int i = 0; i < EPW1; ++i) {
        int e = e0 + i;
        if (e < E) { idx[i] = g_eidx[e]; u[i] = __ldg(&ea[e]); }
        else       { idx[i] = make_int2(0, -1); u[i] = 0.f; }
    }
    float2 f[EPW1];
    #pragma unroll
    for (int i = 0; i < EPW1; ++i)
        f[i] = __half22float2(g_p1[idx[i].x * 32 + lane]);
    #pragma unroll
    for (int i = 0; i < EPW1; ++i)
        if (idx[i].y >= 0)
            atomicAdd(&g_agg1[idx[i].y * 32 + lane], fmaf(u[i], f[i].y, f[i].x));
}

// ---- layer-1 combine: mean + root + bias, relu ----
__global__ void k_combine1(int n) {
    int idx = blockIdx.x * blockDim.x + threadIdx.x;
    if (idx >= n * 32) return;
    int i = idx >> 5;
    float inv = 1.0f / fmaxf(g_deg[i], 1.0f);
    float v = g_agg1[idx] * inv + g_r1[idx];
    g_h[idx] = fmaxf(v, 0.0f);
}

// ---- layer-2 node precompute (padded to 16 cols) ----
__global__ void k_prep2(const float* __restrict__ W2,     // (2,32,10)
                        const float* __restrict__ root2,  // (32,10)
                        const float* __restrict__ b2,
                        int n) {
    __shared__ float sW0[512], sW1[512], sR[512];
    for (int i = threadIdx.x; i < 512; i += blockDim.x) {
        int k = i >> 4, j = i & 15;
        float w0 = 0.f, w1 = 0.f, r = 0.f;
        if (j < 10) {
            w0 = W2[k * 10 + j];
            w1 = W2[320 + k * 10 + j];
            r  = root2[k * 10 + j];
        }
        sW0[i] = w0; sW1[i] = w1; sR[i] = r;
    }
    __syncthreads();
    int lane = threadIdx.x & 31;
    int node = blockIdx.x * (blockDim.x >> 5) + (threadIdx.x >> 5);
    if (node >= n) return;
    float hv = g_h[node * 32 + lane];
    int j = lane & 15;
    float a0 = 0.f, a1 = 0.f, ar = 0.f;
    #pragma unroll
    for (int k = 0; k < 32; ++k) {
        float hk = __shfl_sync(0xffffffffu, hv, k);
        a0 = fmaf(hk, sW0[k * 16 + j], a0);
        a1 = fmaf(hk, sW1[k * 16 + j], a1);
        ar = fmaf(hk, sR [k * 16 + j], ar);
    }
    if (lane < 16) {
        int o = node * 16 + lane;
        g_p2[o] = __floats2half2_rn(a0, a1 - a0);
        g_r2[o] = ar + ((lane < 10) ? b2[lane] : 0.0f);
    }
}

// ---- layer-2 edge scatter: 16-lane sub-warp, 4 edges each, batched ----
#define EPW2 4
__global__ void k_edge2(const float* __restrict__ ea, int E) {
    int tid = blockIdx.x * blockDim.x + threadIdx.x;
    int sw = tid >> 4;
    int sl = tid & 15;
    int e0 = sw * EPW2;
    if (e0 >= E) return;
    int2  idx[EPW2];
    float u  [EPW2];
    #pragma unroll
    for (int i = 0; i < EPW2; ++i) {
        int e = e0 + i;
        if (e < E) { idx[i] = g_eidx[e]; u[i] = __ldg(&ea[e]); }
        else       { idx[i] = make_int2(0, -1); u[i] = 0.f; }
    }
    float2 f[EPW2];
    #pragma unroll
    for (int i = 0; i < EPW2; ++i)
        f[i] = __half22float2(g_p2[idx[i].x * 16 + sl]);   // cols 10..15 are zeros
    #pragma unroll
    for (int i = 0; i < EPW2; ++i)
        if (sl < 10 && idx[i].y >= 0)
            atomicAdd(&g_agg2[idx[i].y * 16 + sl], fmaf(u[i], f[i].y, f[i].x));
}

// ---- layer-2 combine + log_softmax ----
__global__ void k_combine2(float* __restrict__ out, int n) {
    int i = blockIdx.x * blockDim.x + threadIdx.x;
    if (i >= n) return;
    float inv = 1.0f / fmaxf(g_deg[i], 1.0f);
    float z[10];
    float m = -1e30f;
    #pragma unroll
    for (int j = 0; j < 10; ++j) {
        z[j] = g_agg2[i * 16 + j] * inv + g_r2[i * 16 + j];
        m = fmaxf(m, z[j]);
    }
    float s = 0.f;
    #pragma unroll
    for (int j = 0; j < 10; ++j) s += __expf(z[j] - m);
    float l = m + logf(s);
    #pragma unroll
    for (int j = 0; j < 10; ++j) out[i * 10 + j] = z[j] - l;
}

extern "C" void kernel_launch(void* const* d_in, const int* in_sizes, int n_in,
                              void* d_out, int out_size) {
    const float* x     = (const float*)d_in[0];
    const void*  ei    = d_in[1];
    const float* ea    = (const float*)d_in[2];
    const float* W1    = (const float*)d_in[3];
    const float* root1 = (const float*)d_in[4];
    const float* b1    = (const float*)d_in[5];
    const float* W2    = (const float*)d_in[6];
    const float* root2 = (const float*)d_in[7];
    const float* b2    = (const float*)d_in[8];
    float* out = (float*)d_out;

    int N = in_sizes[0] / 32;
    int E = in_sizes[2];

    k_detect<<<1, 1>>>(ei);
    k_zero<<<(N * 32 + 255) / 256, 256>>>(N);
    k_decode<<<(E + 255) / 256, 256>>>(ei, E);
    k_prep1<<<(N + 7) / 8, 256>>>(x, W1, root1, b1, N);
    {
        long long warps = (E + EPW1 - 1) / EPW1;
        long long th = warps * 32;
        k_edge1<<<(int)((th + 255) / 256), 256>>>(ea, E);
    }
    k_combine1<<<(N * 32 + 255) / 256, 256>>>(N);
    k_prep2<<<(N + 7) / 8, 256>>>(W2, root2, b2, N);
    {
        long long subw = (E + EPW2 - 1) / EPW2;
        long long th = subw * 16;
        k_edge2<<<(int)((th + 255) / 256), 256>>>(ea, E);
    }
    k_combine2<<<(N + 255) / 256, 256>>>(out, N);
}